// round 4
// baseline (speedup 1.0000x reference)
#include <cuda_runtime.h>
#include <cuda_bf16.h>
#include <cstdint>

#define B_    4
#define N_    16384
#define C_    64
#define K_    16
#define O_    64
#define RTOT  (B_ * N_)          // 65536 rows
#define TOTSAMP 1048576.0f
#define BN_EPS 1e-5f

__device__ __align__(16) float g_u[RTOT * O_];
__device__ __align__(16) float g_v[RTOT * O_];
__device__ __align__(16) float g_mx[RTOT * O_];
__device__ __align__(16) float g_mn[RTOT * O_];
__device__ float g_sum[O_];
__device__ float g_sq[O_];

typedef unsigned long long ull;

__device__ __forceinline__ ull pack2(float a, float b) {
    ull r; asm("mov.b64 %0, {%1, %2};" : "=l"(r) : "f"(a), "f"(b)); return r;
}
__device__ __forceinline__ void fma2(ull& d, ull a, ull b) {
    asm("fma.rn.f32x2 %0, %1, %2, %0;" : "+l"(d) : "l"(a), "l"(b));
}
__device__ __forceinline__ float2 unpack2(ull v) {
    float2 f; asm("mov.b64 {%0, %1}, %2;" : "=f"(f.x), "=f"(f.y) : "l"(v)); return f;
}

// ---------------------------------------------------------------------------
// K1: [u|v] = x @ [ (W1-W2)^T | W2^T ]  — a 65536x128x64 fp32 GEMM.
// 128 rows x 128 cols per block, 256 threads, 8x8 micro-tile per thread.
// Manual register double-buffering over the c-loop: fragments for c+1 are
// issued before the FMAs for c, hiding the 29-cycle LDS latency with ILP
// rather than occupancy.
// ---------------------------------------------------------------------------
__global__ __launch_bounds__(256, 2) void k_gemm(const float* __restrict__ x,
                                                 const float* __restrict__ w) {
    __shared__ __align__(16) float sW[64][128];  // [c][0:64]=W1-W2, [64:128]=W2
    __shared__ __align__(16) float sX[128][64];  // [row][c]

    int tid = threadIdx.x;
    if (blockIdx.x == 0 && tid < O_) { g_sum[tid] = 0.f; g_sq[tid] = 0.f; }

    // Weights: task (o, c4) loads W1/W2 float4, writes transposed.
    const float4* w4 = (const float4*)w;        // row o = 32 float4
    for (int i = tid; i < 1024; i += 256) {
        int o  = i & 63;
        int c4 = i >> 6;
        float4 w1 = w4[o * 32 + c4];
        float4 w2 = w4[o * 32 + 16 + c4];
        int c = c4 * 4;
        sW[c + 0][o] = w1.x - w2.x;  sW[c + 0][64 + o] = w2.x;
        sW[c + 1][o] = w1.y - w2.y;  sW[c + 1][64 + o] = w2.y;
        sW[c + 2][o] = w1.z - w2.z;  sW[c + 2][64 + o] = w2.z;
        sW[c + 3][o] = w1.w - w2.w;  sW[c + 3][64 + o] = w2.w;
    }
    int rowBase = blockIdx.x * 128;
    const float4* x4 = (const float4*)(x + (size_t)rowBase * 64);
    for (int i = tid; i < 128 * 16; i += 256)
        ((float4*)&sX[0][0])[i] = x4[i];
    __syncthreads();

    int tx = tid & 15, ty = tid >> 4;
    const float* xrow = &sX[ty * 8][0];          // row stride 64 floats
    const float* wcol = &sW[0][0] + tx * 4;      // c stride 128 floats

    ull acc[8][4] = {};          // [row][u0,u1,v0,v1]
    float af[2][8];
    ull   bf[2][4];

#define LOADF(buf, c)                                                        \
    do {                                                                     \
        const float* wp = wcol + (c) * 128;                                  \
        bf[buf][0] = *(const ull*)(wp + 0);                                  \
        bf[buf][1] = *(const ull*)(wp + 2);                                  \
        bf[buf][2] = *(const ull*)(wp + 64);                                 \
        bf[buf][3] = *(const ull*)(wp + 66);                                 \
        _Pragma("unroll")                                                    \
        for (int _i = 0; _i < 8; _i++) af[buf][_i] = xrow[_i * 64 + (c)];    \
    } while (0)

#define COMPUTE(buf)                                                         \
    do {                                                                     \
        _Pragma("unroll")                                                    \
        for (int _i = 0; _i < 8; _i++) {                                     \
            ull aa = pack2(af[buf][_i], af[buf][_i]);                        \
            fma2(acc[_i][0], aa, bf[buf][0]);                                \
            fma2(acc[_i][1], aa, bf[buf][1]);                                \
            fma2(acc[_i][2], aa, bf[buf][2]);                                \
            fma2(acc[_i][3], aa, bf[buf][3]);                                \
        }                                                                    \
    } while (0)

    LOADF(0, 0);
#pragma unroll 7
    for (int cb = 0; cb < 62; cb += 2) {
        LOADF(1, cb + 1);
        COMPUTE(0);
        LOADF(0, cb + 2);
        COMPUTE(1);
    }
    LOADF(1, 63);
    COMPUTE(0);       // c = 62
    COMPUTE(1);       // c = 63
#undef LOADF
#undef COMPUTE

#pragma unroll
    for (int i = 0; i < 8; i++) {
        size_t r = (size_t)rowBase + ty * 8 + i;
        float2 u0 = unpack2(acc[i][0]), u1 = unpack2(acc[i][1]);
        float2 v0 = unpack2(acc[i][2]), v1 = unpack2(acc[i][3]);
        ((float4*)(g_u + r * 64))[tx] = make_float4(u0.x, u0.y, u1.x, u1.y);
        ((float4*)(g_v + r * 64))[tx] = make_float4(v0.x, v0.y, v1.x, v1.y);
    }
}

// ---------------------------------------------------------------------------
// K2: gather (unchanged from R3 — near the LTS cap).
// ---------------------------------------------------------------------------
__global__ __launch_bounds__(256) void k_gather(const int* __restrict__ idx) {
    int tid  = threadIdx.x;
    int lane = tid & 31;
    int half = lane >> 4;
    int c4   = lane & 15;
    int warpId = blockIdx.x * 8 + (tid >> 5);
    int pbase  = warpId * 16;

    float4 cs1 = {0, 0, 0, 0}, cs2 = {0, 0, 0, 0};

    for (int p = 0; p < 16; ++p) {
        int point = pbase + p;
        int b = point >> 14;
        const float4* vb = (const float4*)(g_v + (size_t)b * N_ * O_);
        const int* ip = idx + (size_t)point * K_;

        float4 u = __ldg((const float4*)(g_u + (size_t)point * O_) + c4);

        float4 mx = make_float4(-3.4e38f, -3.4e38f, -3.4e38f, -3.4e38f);
        float4 mn = make_float4( 3.4e38f,  3.4e38f,  3.4e38f,  3.4e38f);
        float4 s1 = {0, 0, 0, 0}, s2 = {0, 0, 0, 0};
#pragma unroll
        for (int s = 0; s < 8; s++) {
            int j = __ldg(&ip[2 * s + half]);
            float4 v = __ldg(vb + (size_t)j * 16 + c4);
            mx.x = fmaxf(mx.x, v.x); mn.x = fminf(mn.x, v.x); s1.x += v.x; s2.x = fmaf(v.x, v.x, s2.x);
            mx.y = fmaxf(mx.y, v.y); mn.y = fminf(mn.y, v.y); s1.y += v.y; s2.y = fmaf(v.y, v.y, s2.y);
            mx.z = fmaxf(mx.z, v.z); mn.z = fminf(mn.z, v.z); s1.z += v.z; s2.z = fmaf(v.z, v.z, s2.z);
            mx.w = fmaxf(mx.w, v.w); mn.w = fminf(mn.w, v.w); s1.w += v.w; s2.w = fmaf(v.w, v.w, s2.w);
        }
        mx.x = fmaxf(mx.x, __shfl_xor_sync(0xffffffffu, mx.x, 16));
        mx.y = fmaxf(mx.y, __shfl_xor_sync(0xffffffffu, mx.y, 16));
        mx.z = fmaxf(mx.z, __shfl_xor_sync(0xffffffffu, mx.z, 16));
        mx.w = fmaxf(mx.w, __shfl_xor_sync(0xffffffffu, mx.w, 16));
        mn.x = fminf(mn.x, __shfl_xor_sync(0xffffffffu, mn.x, 16));
        mn.y = fminf(mn.y, __shfl_xor_sync(0xffffffffu, mn.y, 16));
        mn.z = fminf(mn.z, __shfl_xor_sync(0xffffffffu, mn.z, 16));
        mn.w = fminf(mn.w, __shfl_xor_sync(0xffffffffu, mn.w, 16));

        if (half == 0) {
            ((float4*)(g_mx + (size_t)point * O_))[c4] =
                make_float4(u.x + mx.x, u.y + mx.y, u.z + mx.z, u.w + mx.w);
            ((float4*)(g_mn + (size_t)point * O_))[c4] =
                make_float4(u.x + mn.x, u.y + mn.y, u.z + mn.z, u.w + mn.w);
        }

        cs1.x += 8.f * u.x + s1.x;  cs2.x += fmaf(8.f * u.x, u.x, fmaf(2.f * u.x, s1.x, s2.x));
        cs1.y += 8.f * u.y + s1.y;  cs2.y += fmaf(8.f * u.y, u.y, fmaf(2.f * u.y, s1.y, s2.y));
        cs1.z += 8.f * u.z + s1.z;  cs2.z += fmaf(8.f * u.z, u.z, fmaf(2.f * u.z, s1.z, s2.z));
        cs1.w += 8.f * u.w + s1.w;  cs2.w += fmaf(8.f * u.w, u.w, fmaf(2.f * u.w, s1.w, s2.w));
    }

    __shared__ float ssum[O_], ssq[O_];
    if (tid < O_) { ssum[tid] = 0.f; ssq[tid] = 0.f; }
    __syncthreads();
    int cb = c4 * 4;
    atomicAdd(&ssum[cb + 0], cs1.x); atomicAdd(&ssq[cb + 0], cs2.x);
    atomicAdd(&ssum[cb + 1], cs1.y); atomicAdd(&ssq[cb + 1], cs2.y);
    atomicAdd(&ssum[cb + 2], cs1.z); atomicAdd(&ssq[cb + 2], cs2.z);
    atomicAdd(&ssum[cb + 3], cs1.w); atomicAdd(&ssq[cb + 3], cs2.w);
    __syncthreads();
    if (tid < O_) {
        atomicAdd(&g_sum[tid], ssum[tid]);
        atomicAdd(&g_sq[tid],  ssq[tid]);
    }
}

// ---------------------------------------------------------------------------
// K3: fused stats + epilogue (unchanged).
// ---------------------------------------------------------------------------
__global__ __launch_bounds__(256) void k_out(const float* __restrict__ gamma,
                                             const float* __restrict__ beta,
                                             float* __restrict__ out) {
    __shared__ __align__(16) float sc[O_];
    __shared__ __align__(16) float sh[O_];
    __shared__ int negFlag;
    int tid = threadIdx.x;
    if (tid == 0) negFlag = 0;
    __syncthreads();
    if (tid < O_) {
        float inv  = 1.0f / TOTSAMP;
        float mean = g_sum[tid] * inv;
        float var  = g_sq[tid] * inv - mean * mean;
        float s    = rsqrtf(var + BN_EPS) * gamma[tid];
        sc[tid] = s;
        sh[tid] = beta[tid] - mean * s;
        if (s < 0.f) atomicOr(&negFlag, 1);
    }
    __syncthreads();

    size_t i4 = (size_t)blockIdx.x * 256 + tid;
    int o4 = (int)(i4 & 15);
    float4 s4 = ((const float4*)sc)[o4];
    float4 b4 = ((const float4*)sh)[o4];

    float4 m;
    if (!negFlag) {
        m = __ldg((const float4*)g_mx + i4);
    } else {
        float4 a = __ldg((const float4*)g_mx + i4);
        float4 c = __ldg((const float4*)g_mn + i4);
        m.x = (s4.x >= 0.f) ? a.x : c.x;
        m.y = (s4.y >= 0.f) ? a.y : c.y;
        m.z = (s4.z >= 0.f) ? a.z : c.z;
        m.w = (s4.w >= 0.f) ? a.w : c.w;
    }
    float4 r;
    r.x = fmaxf(fmaf(m.x, s4.x, b4.x), 0.f);
    r.y = fmaxf(fmaf(m.y, s4.y, b4.y), 0.f);
    r.z = fmaxf(fmaf(m.z, s4.z, b4.z), 0.f);
    r.w = fmaxf(fmaf(m.w, s4.w, b4.w), 0.f);
    ((float4*)out)[i4] = r;
}

extern "C" void kernel_launch(void* const* d_in, const int* in_sizes, int n_in,
                              void* d_out, int out_size) {
    const float* x     = (const float*)d_in[0];
    const int*   idx   = (const int*)  d_in[1];
    const float* w     = (const float*)d_in[2];
    const float* gamma = (const float*)d_in[3];
    const float* beta  = (const float*)d_in[4];
    float* out = (float*)d_out;

    k_gemm  <<<RTOT / 128, 256>>>(x, w);
    k_gather<<<RTOT / (8 * 16), 256>>>(idx);
    k_out   <<<(RTOT * O_ / 4) / 256, 256>>>(gamma, beta, out);
}

// round 6
// speedup vs baseline: 1.0349x; 1.0349x over previous
#include <cuda_runtime.h>
#include <cuda_bf16.h>
#include <cstdint>

#define B_    4
#define N_    16384
#define C_    64
#define K_    16
#define O_    64
#define RTOT  (B_ * N_)          // 65536 rows
#define TOTSAMP 1048576.0f
#define BN_EPS 1e-5f

__device__ __align__(16) float g_u[RTOT * O_];
__device__ __align__(16) float g_v[RTOT * O_];
__device__ __align__(16) float g_mx[RTOT * O_];
__device__ __align__(16) float g_mn[RTOT * O_];
__device__ float g_sum[O_];
__device__ float g_sq[O_];

// ---------------------------------------------------------------------------
// tf32 helpers (baseline sm_80 PTX — no arch-specific features)
// ---------------------------------------------------------------------------
__device__ __forceinline__ float tf32f(float a) {
    uint32_t u;
    asm("cvt.rna.tf32.f32 %0, %1;" : "=r"(u) : "f"(a));
    return __uint_as_float(u);
}
__device__ __forceinline__ void mma_tf32(float d[4], const uint32_t a[4],
                                         const uint32_t b0, const uint32_t b1) {
    asm volatile(
        "mma.sync.aligned.m16n8k8.row.col.f32.tf32.tf32.f32 "
        "{%0,%1,%2,%3}, {%4,%5,%6,%7}, {%8,%9}, {%0,%1,%2,%3};"
        : "+f"(d[0]), "+f"(d[1]), "+f"(d[2]), "+f"(d[3])
        : "r"(a[0]), "r"(a[1]), "r"(a[2]), "r"(a[3]), "r"(b0), "r"(b1));
}

// smem layout (dynamic): raw x tile + fragment-ordered split weights
#define XPITCH 68
#define OFF_X   0                               // float[128][68]  = 34816 B
#define OFF_BH  34816                           // float2[8][16][32] = 32768 B
#define OFF_BL  (34816 + 32768)                 // float2[8][16][32] = 32768 B
#define SMEM_GEMM (34816 + 65536)               // 100352 B

// ---------------------------------------------------------------------------
// K1: [u|v] = x @ [ (W1-W2)^T | W2^T ] — 65536x128x64 GEMM via mma.sync
// tf32 with 3xTF32 split (fp32 accuracy). 256 threads = 8 warps; warp (rg,cg)
// computes rows rg*32..+31, cols cg*64..+63 (cg=0 -> g_u, cg=1 -> g_v).
// ---------------------------------------------------------------------------
__global__ __launch_bounds__(256, 2) void k_gemm(const float* __restrict__ x,
                                                 const float* __restrict__ w) {
    extern __shared__ __align__(16) char sm[];
    float*  sX  = (float*)(sm + OFF_X);
    float2* sBh = (float2*)(sm + OFF_BH);
    float2* sBl = (float2*)(sm + OFF_BL);

    int tid = threadIdx.x;
    int lane = tid & 31, wid = tid >> 5;
    int rg = wid >> 1, cg = wid & 1;

    if (blockIdx.x == 0 && tid < O_) { g_sum[tid] = 0.f; g_sq[tid] = 0.f; }

    // ---- stage x tile (raw fp32) into padded smem ----
    int rowBase = blockIdx.x * 128;
    const float4* x4 = (const float4*)(x + (size_t)rowBase * 64);
    for (int i = tid; i < 128 * 16; i += 256) {
        int r = i >> 4, c4 = i & 15;
        float4 v = x4[i];
        float* p = sX + r * XPITCH + c4 * 4;
        p[0] = v.x; p[1] = v.y; p[2] = v.z; p[3] = v.w;
    }

    // ---- stage split weights in mma-fragment order ----
    // index i -> (ks, t, lane): b0 = W'[n][k], b1 = W'[n][k+4]
    // n = t*8 + (lane>>2), k = ks*8 + (lane&3)
    // W' rows 0..63 = W1-W2, rows 64..127 = W2
    for (int i = tid; i < 8 * 16 * 32; i += 256) {
        int l  = i & 31;
        int t  = (i >> 5) & 15;
        int ks = i >> 9;
        int n = t * 8 + (l >> 2);
        int k = ks * 8 + (l & 3);
        float v0, v1;
        if (n < 64) {
            v0 = w[n * 128 + k]     - w[n * 128 + 64 + k];
            v1 = w[n * 128 + k + 4] - w[n * 128 + 64 + k + 4];
        } else {
            v0 = w[(n - 64) * 128 + 64 + k];
            v1 = w[(n - 64) * 128 + 64 + k + 4];
        }
        float h0 = tf32f(v0), h1 = tf32f(v1);
        sBh[i] = make_float2(h0, h1);
        sBl[i] = make_float2(tf32f(v0 - h0), tf32f(v1 - h1));
    }
    __syncthreads();

    float acc[8][2][4] = {};    // [n-tile][m-tile][frag]

    int arow0 = rg * 32 + (lane >> 2);     // + m*16 (+8 for frag rows)
    int acol0 = lane & 3;                  // + ks*8 (+4)

#pragma unroll 1
    for (int ks = 0; ks < 8; ks++) {
        uint32_t ah[2][4], al[2][4];
#pragma unroll
        for (int m = 0; m < 2; m++) {
#pragma unroll
            for (int i = 0; i < 4; i++) {
                int r = arow0 + m * 16 + (i & 1) * 8;
                int c = acol0 + ks * 8 + (i >> 1) * 4;
                float xv = sX[r * XPITCH + c];
                float hi = tf32f(xv);
                ah[m][i] = __float_as_uint(hi);
                al[m][i] = __float_as_uint(tf32f(xv - hi));
            }
        }
        const float2* bh = sBh + (ks * 16 + cg * 8) * 32 + lane;
        const float2* bl = sBl + (ks * 16 + cg * 8) * 32 + lane;
#pragma unroll
        for (int t = 0; t < 8; t++) {
            float2 h = bh[t * 32];
            float2 l = bl[t * 32];
            uint32_t bh0 = __float_as_uint(h.x), bh1 = __float_as_uint(h.y);
            uint32_t bl0 = __float_as_uint(l.x), bl1 = __float_as_uint(l.y);
            mma_tf32(acc[t][0], ah[0], bh0, bh1);
            mma_tf32(acc[t][1], ah[1], bh0, bh1);
            mma_tf32(acc[t][0], ah[0], bl0, bl1);
            mma_tf32(acc[t][1], ah[1], bl0, bl1);
            mma_tf32(acc[t][0], al[0], bh0, bh1);
            mma_tf32(acc[t][1], al[1], bh0, bh1);
        }
    }

    // ---- store D: cg=0 -> g_u, cg=1 -> g_v ----
    float* dst = cg ? g_v : g_u;
#pragma unroll
    for (int t = 0; t < 8; t++) {
#pragma unroll
        for (int m = 0; m < 2; m++) {
            int row = rowBase + rg * 32 + m * 16 + (lane >> 2);
            int col = t * 8 + (lane & 3) * 2;
            *(float2*)(dst + (size_t)row * 64 + col) =
                make_float2(acc[t][m][0], acc[t][m][1]);
            *(float2*)(dst + (size_t)(row + 8) * 64 + col) =
                make_float2(acc[t][m][2], acc[t][m][3]);
        }
    }
}

// ---------------------------------------------------------------------------
// K2: gather (unchanged — near LTS cap).
// ---------------------------------------------------------------------------
__global__ __launch_bounds__(256) void k_gather(const int* __restrict__ idx) {
    int tid  = threadIdx.x;
    int lane = tid & 31;
    int half = lane >> 4;
    int c4   = lane & 15;
    int warpId = blockIdx.x * 8 + (tid >> 5);
    int pbase  = warpId * 16;

    float4 cs1 = {0, 0, 0, 0}, cs2 = {0, 0, 0, 0};

    for (int p = 0; p < 16; ++p) {
        int point = pbase + p;
        int b = point >> 14;
        const float4* vb = (const float4*)(g_v + (size_t)b * N_ * O_);
        const int* ip = idx + (size_t)point * K_;

        float4 u = __ldg((const float4*)(g_u + (size_t)point * O_) + c4);

        float4 mx = make_float4(-3.4e38f, -3.4e38f, -3.4e38f, -3.4e38f);
        float4 mn = make_float4( 3.4e38f,  3.4e38f,  3.4e38f,  3.4e38f);
        float4 s1 = {0, 0, 0, 0}, s2 = {0, 0, 0, 0};
#pragma unroll
        for (int s = 0; s < 8; s++) {
            int j = __ldg(&ip[2 * s + half]);
            float4 v = __ldg(vb + (size_t)j * 16 + c4);
            mx.x = fmaxf(mx.x, v.x); mn.x = fminf(mn.x, v.x); s1.x += v.x; s2.x = fmaf(v.x, v.x, s2.x);
            mx.y = fmaxf(mx.y, v.y); mn.y = fminf(mn.y, v.y); s1.y += v.y; s2.y = fmaf(v.y, v.y, s2.y);
            mx.z = fmaxf(mx.z, v.z); mn.z = fminf(mn.z, v.z); s1.z += v.z; s2.z = fmaf(v.z, v.z, s2.z);
            mx.w = fmaxf(mx.w, v.w); mn.w = fminf(mn.w, v.w); s1.w += v.w; s2.w = fmaf(v.w, v.w, s2.w);
        }
        mx.x = fmaxf(mx.x, __shfl_xor_sync(0xffffffffu, mx.x, 16));
        mx.y = fmaxf(mx.y, __shfl_xor_sync(0xffffffffu, mx.y, 16));
        mx.z = fmaxf(mx.z, __shfl_xor_sync(0xffffffffu, mx.z, 16));
        mx.w = fmaxf(mx.w, __shfl_xor_sync(0xffffffffu, mx.w, 16));
        mn.x = fminf(mn.x, __shfl_xor_sync(0xffffffffu, mn.x, 16));
        mn.y = fminf(mn.y, __shfl_xor_sync(0xffffffffu, mn.y, 16));
        mn.z = fminf(mn.z, __shfl_xor_sync(0xffffffffu, mn.z, 16));
        mn.w = fminf(mn.w, __shfl_xor_sync(0xffffffffu, mn.w, 16));

        if (half == 0) {
            ((float4*)(g_mx + (size_t)point * O_))[c4] =
                make_float4(u.x + mx.x, u.y + mx.y, u.z + mx.z, u.w + mx.w);
            ((float4*)(g_mn + (size_t)point * O_))[c4] =
                make_float4(u.x + mn.x, u.y + mn.y, u.z + mn.z, u.w + mn.w);
        }

        cs1.x += 8.f * u.x + s1.x;  cs2.x += fmaf(8.f * u.x, u.x, fmaf(2.f * u.x, s1.x, s2.x));
        cs1.y += 8.f * u.y + s1.y;  cs2.y += fmaf(8.f * u.y, u.y, fmaf(2.f * u.y, s1.y, s2.y));
        cs1.z += 8.f * u.z + s1.z;  cs2.z += fmaf(8.f * u.z, u.z, fmaf(2.f * u.z, s1.z, s2.z));
        cs1.w += 8.f * u.w + s1.w;  cs2.w += fmaf(8.f * u.w, u.w, fmaf(2.f * u.w, s1.w, s2.w));
    }

    __shared__ float ssum[O_], ssq[O_];
    if (tid < O_) { ssum[tid] = 0.f; ssq[tid] = 0.f; }
    __syncthreads();
    int cb = c4 * 4;
    atomicAdd(&ssum[cb + 0], cs1.x); atomicAdd(&ssq[cb + 0], cs2.x);
    atomicAdd(&ssum[cb + 1], cs1.y); atomicAdd(&ssq[cb + 1], cs2.y);
    atomicAdd(&ssum[cb + 2], cs1.z); atomicAdd(&ssq[cb + 2], cs2.z);
    atomicAdd(&ssum[cb + 3], cs1.w); atomicAdd(&ssq[cb + 3], cs2.w);
    __syncthreads();
    if (tid < O_) {
        atomicAdd(&g_sum[tid], ssum[tid]);
        atomicAdd(&g_sq[tid],  ssq[tid]);
    }
}

// ---------------------------------------------------------------------------
// K3: fused stats + epilogue (unchanged).
// ---------------------------------------------------------------------------
__global__ __launch_bounds__(256) void k_out(const float* __restrict__ gamma,
                                             const float* __restrict__ beta,
                                             float* __restrict__ out) {
    __shared__ __align__(16) float sc[O_];
    __shared__ __align__(16) float sh[O_];
    __shared__ int negFlag;
    int tid = threadIdx.x;
    if (tid == 0) negFlag = 0;
    __syncthreads();
    if (tid < O_) {
        float inv  = 1.0f / TOTSAMP;
        float mean = g_sum[tid] * inv;
        float var  = g_sq[tid] * inv - mean * mean;
        float s    = rsqrtf(var + BN_EPS) * gamma[tid];
        sc[tid] = s;
        sh[tid] = beta[tid] - mean * s;
        if (s < 0.f) atomicOr(&negFlag, 1);
    }
    __syncthreads();

    size_t i4 = (size_t)blockIdx.x * 256 + tid;
    int o4 = (int)(i4 & 15);
    float4 s4 = ((const float4*)sc)[o4];
    float4 b4 = ((const float4*)sh)[o4];

    float4 m;
    if (!negFlag) {
        m = __ldg((const float4*)g_mx + i4);
    } else {
        float4 a = __ldg((const float4*)g_mx + i4);
        float4 c = __ldg((const float4*)g_mn + i4);
        m.x = (s4.x >= 0.f) ? a.x : c.x;
        m.y = (s4.y >= 0.f) ? a.y : c.y;
        m.z = (s4.z >= 0.f) ? a.z : c.z;
        m.w = (s4.w >= 0.f) ? a.w : c.w;
    }
    float4 r;
    r.x = fmaxf(fmaf(m.x, s4.x, b4.x), 0.f);
    r.y = fmaxf(fmaf(m.y, s4.y, b4.y), 0.f);
    r.z = fmaxf(fmaf(m.z, s4.z, b4.z), 0.f);
    r.w = fmaxf(fmaf(m.w, s4.w, b4.w), 0.f);
    ((float4*)out)[i4] = r;
}

extern "C" void kernel_launch(void* const* d_in, const int* in_sizes, int n_in,
                              void* d_out, int out_size) {
    const float* x     = (const float*)d_in[0];
    const int*   idx   = (const int*)  d_in[1];
    const float* w     = (const float*)d_in[2];
    const float* gamma = (const float*)d_in[3];
    const float* beta  = (const float*)d_in[4];
    float* out = (float*)d_out;

    cudaFuncSetAttribute(k_gemm, cudaFuncAttributeMaxDynamicSharedMemorySize, SMEM_GEMM);

    k_gemm  <<<RTOT / 128, 256, SMEM_GEMM>>>(x, w);
    k_gather<<<RTOT / (8 * 16), 256>>>(idx);
    k_out   <<<(RTOT * O_ / 4) / 256, 256>>>(gamma, beta, out);
}

// round 7
// speedup vs baseline: 1.1867x; 1.1468x over previous
#include <cuda_runtime.h>
#include <cuda_bf16.h>
#include <cstdint>

#define B_    4
#define N_    16384
#define C_    64
#define K_    16
#define O_    64
#define RTOT  (B_ * N_)          // 65536 rows
#define TOTSAMP 1048576.0f
#define BN_EPS 1e-5f

__device__ __align__(16) float g_u[RTOT * O_];
__device__ __align__(16) float g_v[RTOT * O_];
__device__ __align__(16) float g_mx[RTOT * O_];
__device__ __align__(16) float g_mn[RTOT * O_];
__device__ float g_sum[O_];
__device__ float g_sq[O_];
// fragment-ordered split weights: [ks(8)][tcol(16)][lane(32)] float2
__device__ __align__(16) float2 g_Bh[8 * 16 * 32];
__device__ __align__(16) float2 g_Bl[8 * 16 * 32];

// ---------------------------------------------------------------------------
// tf32 helpers (baseline sm_80 PTX)
// ---------------------------------------------------------------------------
__device__ __forceinline__ float tf32f(float a) {
    uint32_t u;
    asm("cvt.rna.tf32.f32 %0, %1;" : "=r"(u) : "f"(a));
    return __uint_as_float(u);
}
__device__ __forceinline__ void mma_tf32(float d[4], const uint32_t a[4],
                                         const uint32_t b0, const uint32_t b1) {
    asm volatile(
        "mma.sync.aligned.m16n8k8.row.col.f32.tf32.tf32.f32 "
        "{%0,%1,%2,%3}, {%4,%5,%6,%7}, {%8,%9}, {%0,%1,%2,%3};"
        : "+f"(d[0]), "+f"(d[1]), "+f"(d[2]), "+f"(d[3])
        : "r"(a[0]), "r"(a[1]), "r"(a[2]), "r"(a[3]), "r"(b0), "r"(b1));
}

// ---------------------------------------------------------------------------
// K0: pre-split weights into mma-fragment order (hi/lo tf32) + zero stats.
// entry i -> (ks,t,lane): n = t*8 + (lane>>2), k = ks*8 + (lane&3)
// b0 = W'[n][k], b1 = W'[n][k+4];  W' rows 0..63 = W1-W2, 64..127 = W2.
// ---------------------------------------------------------------------------
__global__ void k_prep(const float* __restrict__ w) {
    int i = blockIdx.x * 256 + threadIdx.x;
    if (i < 64) { g_sum[i] = 0.f; g_sq[i] = 0.f; }
    if (i >= 8 * 16 * 32) return;
    int l  = i & 31;
    int t  = (i >> 5) & 15;
    int ks = i >> 9;
    int n = t * 8 + (l >> 2);
    int k = ks * 8 + (l & 3);
    float v0, v1;
    if (n < 64) {
        v0 = w[n * 128 + k]     - w[n * 128 + 64 + k];
        v1 = w[n * 128 + k + 4] - w[n * 128 + 64 + k + 4];
    } else {
        v0 = w[(n - 64) * 128 + 64 + k];
        v1 = w[(n - 64) * 128 + 64 + k + 4];
    }
    float h0 = tf32f(v0), h1 = tf32f(v1);
    g_Bh[i] = make_float2(h0, h1);
    g_Bl[i] = make_float2(tf32f(v0 - h0), tf32f(v1 - h1));
}

// ---------------------------------------------------------------------------
// K1: [u|v] = x @ [ (W1-W2)^T | W2^T ] — mma.sync tf32, 3xTF32 split.
// CTA: 64 rows x 128 cols, 8 warps; warp (rg=wid&3, cg=wid>>2) owns
// rows rg*16..+15 and cols cg*64..+63 (cg=0 -> g_u, cg=1 -> g_v).
// 32 accumulator regs/thread -> 3 CTAs/SM. B frags via __ldg (L1-resident).
// ---------------------------------------------------------------------------
#define XPITCH 68
__global__ __launch_bounds__(256, 3) void k_gemm(const float* __restrict__ x) {
    __shared__ float sX[64][XPITCH];

    int tid = threadIdx.x;
    int lane = tid & 31, wid = tid >> 5;
    int rg = wid & 3, cg = wid >> 2;

    // stage x tile
    int rowBase = blockIdx.x * 64;
    const float4* x4 = (const float4*)(x + (size_t)rowBase * 64);
    for (int i = tid; i < 64 * 16; i += 256) {
        int r = i >> 4, c4 = i & 15;
        float4 v = x4[i];
        float* p = &sX[r][c4 * 4];
        p[0] = v.x; p[1] = v.y; p[2] = v.z; p[3] = v.w;
    }
    __syncthreads();

    float acc[8][4] = {};
    int arow = rg * 16 + (lane >> 2);
    int acol = lane & 3;
    const float2* bhBase = g_Bh + cg * 8 * 32 + lane;
    const float2* blBase = g_Bl + cg * 8 * 32 + lane;

#pragma unroll
    for (int ks = 0; ks < 8; ks++) {
        uint32_t ah[4], al[4];
        {
            float x0 = sX[arow][acol + ks * 8];
            float x1 = sX[arow + 8][acol + ks * 8];
            float x2 = sX[arow][acol + 4 + ks * 8];
            float x3 = sX[arow + 8][acol + 4 + ks * 8];
            float h0 = tf32f(x0), h1 = tf32f(x1), h2 = tf32f(x2), h3 = tf32f(x3);
            ah[0] = __float_as_uint(h0); al[0] = __float_as_uint(tf32f(x0 - h0));
            ah[1] = __float_as_uint(h1); al[1] = __float_as_uint(tf32f(x1 - h1));
            ah[2] = __float_as_uint(h2); al[2] = __float_as_uint(tf32f(x2 - h2));
            ah[3] = __float_as_uint(h3); al[3] = __float_as_uint(tf32f(x3 - h3));
        }
        const float2* bh = bhBase + ks * 16 * 32;
        const float2* bl = blBase + ks * 16 * 32;
#pragma unroll
        for (int t = 0; t < 8; t++) {
            float2 h = __ldg(bh + t * 32);
            float2 l = __ldg(bl + t * 32);
            uint32_t b0 = __float_as_uint(h.x), b1 = __float_as_uint(h.y);
            uint32_t c0 = __float_as_uint(l.x), c1 = __float_as_uint(l.y);
            mma_tf32(acc[t], ah, b0, b1);
            mma_tf32(acc[t], ah, c0, c1);
            mma_tf32(acc[t], al, b0, b1);
        }
    }

    float* dst = cg ? g_v : g_u;
    int row = rowBase + rg * 16 + (lane >> 2);
    int col = (lane & 3) * 2;
#pragma unroll
    for (int t = 0; t < 8; t++) {
        *(float2*)(dst + (size_t)row * 64 + t * 8 + col) =
            make_float2(acc[t][0], acc[t][1]);
        *(float2*)(dst + (size_t)(row + 8) * 64 + t * 8 + col) =
            make_float2(acc[t][2], acc[t][3]);
    }
}

// ---------------------------------------------------------------------------
// K2: gather (unchanged — near LTS cap).
// ---------------------------------------------------------------------------
__global__ __launch_bounds__(256) void k_gather(const int* __restrict__ idx) {
    int tid  = threadIdx.x;
    int lane = tid & 31;
    int half = lane >> 4;
    int c4   = lane & 15;
    int warpId = blockIdx.x * 8 + (tid >> 5);
    int pbase  = warpId * 16;

    float4 cs1 = {0, 0, 0, 0}, cs2 = {0, 0, 0, 0};

    for (int p = 0; p < 16; ++p) {
        int point = pbase + p;
        int b = point >> 14;
        const float4* vb = (const float4*)(g_v + (size_t)b * N_ * O_);
        const int* ip = idx + (size_t)point * K_;

        float4 u = __ldg((const float4*)(g_u + (size_t)point * O_) + c4);

        float4 mx = make_float4(-3.4e38f, -3.4e38f, -3.4e38f, -3.4e38f);
        float4 mn = make_float4( 3.4e38f,  3.4e38f,  3.4e38f,  3.4e38f);
        float4 s1 = {0, 0, 0, 0}, s2 = {0, 0, 0, 0};
#pragma unroll
        for (int s = 0; s < 8; s++) {
            int j = __ldg(&ip[2 * s + half]);
            float4 v = __ldg(vb + (size_t)j * 16 + c4);
            mx.x = fmaxf(mx.x, v.x); mn.x = fminf(mn.x, v.x); s1.x += v.x; s2.x = fmaf(v.x, v.x, s2.x);
            mx.y = fmaxf(mx.y, v.y); mn.y = fminf(mn.y, v.y); s1.y += v.y; s2.y = fmaf(v.y, v.y, s2.y);
            mx.z = fmaxf(mx.z, v.z); mn.z = fminf(mn.z, v.z); s1.z += v.z; s2.z = fmaf(v.z, v.z, s2.z);
            mx.w = fmaxf(mx.w, v.w); mn.w = fminf(mn.w, v.w); s1.w += v.w; s2.w = fmaf(v.w, v.w, s2.w);
        }
        mx.x = fmaxf(mx.x, __shfl_xor_sync(0xffffffffu, mx.x, 16));
        mx.y = fmaxf(mx.y, __shfl_xor_sync(0xffffffffu, mx.y, 16));
        mx.z = fmaxf(mx.z, __shfl_xor_sync(0xffffffffu, mx.z, 16));
        mx.w = fmaxf(mx.w, __shfl_xor_sync(0xffffffffu, mx.w, 16));
        mn.x = fminf(mn.x, __shfl_xor_sync(0xffffffffu, mn.x, 16));
        mn.y = fminf(mn.y, __shfl_xor_sync(0xffffffffu, mn.y, 16));
        mn.z = fminf(mn.z, __shfl_xor_sync(0xffffffffu, mn.z, 16));
        mn.w = fminf(mn.w, __shfl_xor_sync(0xffffffffu, mn.w, 16));

        if (half == 0) {
            ((float4*)(g_mx + (size_t)point * O_))[c4] =
                make_float4(u.x + mx.x, u.y + mx.y, u.z + mx.z, u.w + mx.w);
            ((float4*)(g_mn + (size_t)point * O_))[c4] =
                make_float4(u.x + mn.x, u.y + mn.y, u.z + mn.z, u.w + mn.w);
        }

        cs1.x += 8.f * u.x + s1.x;  cs2.x += fmaf(8.f * u.x, u.x, fmaf(2.f * u.x, s1.x, s2.x));
        cs1.y += 8.f * u.y + s1.y;  cs2.y += fmaf(8.f * u.y, u.y, fmaf(2.f * u.y, s1.y, s2.y));
        cs1.z += 8.f * u.z + s1.z;  cs2.z += fmaf(8.f * u.z, u.z, fmaf(2.f * u.z, s1.z, s2.z));
        cs1.w += 8.f * u.w + s1.w;  cs2.w += fmaf(8.f * u.w, u.w, fmaf(2.f * u.w, s1.w, s2.w));
    }

    __shared__ float ssum[O_], ssq[O_];
    if (tid < O_) { ssum[tid] = 0.f; ssq[tid] = 0.f; }
    __syncthreads();
    int cb = c4 * 4;
    atomicAdd(&ssum[cb + 0], cs1.x); atomicAdd(&ssq[cb + 0], cs2.x);
    atomicAdd(&ssum[cb + 1], cs1.y); atomicAdd(&ssq[cb + 1], cs2.y);
    atomicAdd(&ssum[cb + 2], cs1.z); atomicAdd(&ssq[cb + 2], cs2.z);
    atomicAdd(&ssum[cb + 3], cs1.w); atomicAdd(&ssq[cb + 3], cs2.w);
    __syncthreads();
    if (tid < O_) {
        atomicAdd(&g_sum[tid], ssum[tid]);
        atomicAdd(&g_sq[tid],  ssq[tid]);
    }
}

// ---------------------------------------------------------------------------
// K3: fused stats + epilogue (unchanged).
// ---------------------------------------------------------------------------
__global__ __launch_bounds__(256) void k_out(const float* __restrict__ gamma,
                                             const float* __restrict__ beta,
                                             float* __restrict__ out) {
    __shared__ __align__(16) float sc[O_];
    __shared__ __align__(16) float sh[O_];
    __shared__ int negFlag;
    int tid = threadIdx.x;
    if (tid == 0) negFlag = 0;
    __syncthreads();
    if (tid < O_) {
        float inv  = 1.0f / TOTSAMP;
        float mean = g_sum[tid] * inv;
        float var  = g_sq[tid] * inv - mean * mean;
        float s    = rsqrtf(var + BN_EPS) * gamma[tid];
        sc[tid] = s;
        sh[tid] = beta[tid] - mean * s;
        if (s < 0.f) atomicOr(&negFlag, 1);
    }
    __syncthreads();

    size_t i4 = (size_t)blockIdx.x * 256 + tid;
    int o4 = (int)(i4 & 15);
    float4 s4 = ((const float4*)sc)[o4];
    float4 b4 = ((const float4*)sh)[o4];

    float4 m;
    if (!negFlag) {
        m = __ldg((const float4*)g_mx + i4);
    } else {
        float4 a = __ldg((const float4*)g_mx + i4);
        float4 c = __ldg((const float4*)g_mn + i4);
        m.x = (s4.x >= 0.f) ? a.x : c.x;
        m.y = (s4.y >= 0.f) ? a.y : c.y;
        m.z = (s4.z >= 0.f) ? a.z : c.z;
        m.w = (s4.w >= 0.f) ? a.w : c.w;
    }
    float4 r;
    r.x = fmaxf(fmaf(m.x, s4.x, b4.x), 0.f);
    r.y = fmaxf(fmaf(m.y, s4.y, b4.y), 0.f);
    r.z = fmaxf(fmaf(m.z, s4.z, b4.z), 0.f);
    r.w = fmaxf(fmaf(m.w, s4.w, b4.w), 0.f);
    ((float4*)out)[i4] = r;
}

extern "C" void kernel_launch(void* const* d_in, const int* in_sizes, int n_in,
                              void* d_out, int out_size) {
    const float* x     = (const float*)d_in[0];
    const int*   idx   = (const int*)  d_in[1];
    const float* w     = (const float*)d_in[2];
    const float* gamma = (const float*)d_in[3];
    const float* beta  = (const float*)d_in[4];
    float* out = (float*)d_out;

    k_prep  <<<16, 256>>>(w);
    k_gemm  <<<RTOT / 64, 256>>>(x);
    k_gather<<<RTOT / (8 * 16), 256>>>(idx);
    k_out   <<<(RTOT * O_ / 4) / 256, 256>>>(gamma, beta, out);
}